// round 9
// baseline (speedup 1.0000x reference)
#include <cuda_runtime.h>
#include <cuda_bf16.h>
#include <cstdint>

#define N_NODES 50000
#define D 128
#define N_EDGES 625000
#define SCAN_BLK 256
#define N_SCAN_BLOCKS ((N_NODES + SCAN_BLK - 1) / SCAN_BLK)   // 196

// Scratch (no cudaMalloc allowed)
__device__ float g_mean[(size_t)N_NODES * D];            // 25.6 MB: mean of y
__device__ __nv_bfloat16 g_y[(size_t)N_NODES * D];       // 12.8 MB: y = x@W_l (bf16)
__device__ int   g_cnt[N_NODES];
__device__ int   g_start[N_NODES];
__device__ int   g_pos[N_NODES];
__device__ int   g_bsum[N_SCAN_BLOCKS];
__device__ int   g_boff[N_SCAN_BLOCKS];
__device__ int   g_esrc[N_EDGES];
// Pre-swizzled bf16 weight images: [phase][32KB], phase 0 = W_l^T, 1 = W_r^T
__device__ __align__(16) uint8_t g_img_hi[2][32768];
__device__ __align__(16) uint8_t g_img_lo[2][32768];

// ---------------------------------------------------------------------------
// helpers
// ---------------------------------------------------------------------------
__device__ __forceinline__ uint32_t smem_to_u32(const void* p) {
    uint32_t a;
    asm("{ .reg .u64 t; cvta.to.shared.u64 t, %1; cvt.u32.u64 %0, t; }"
        : "=r"(a) : "l"(p));
    return a;
}
#define SMEM_SWIZZLE_128B(o) ((o) ^ (((o) >> 3) & 0x70))

__device__ __forceinline__ uint32_t tile_off(int row, int col) {
    return (uint32_t)((((row >> 3) + ((col >> 6) << 4)) << 10) +
                      ((row & 7) << 7) + ((col & 63) << 1));
}

__device__ __forceinline__ uint32_t packbf(__nv_bfloat16 a, __nv_bfloat16 b) {
    __nv_bfloat162 t;
    t.x = a; t.y = b;
    return *reinterpret_cast<uint32_t*>(&t);
}

__device__ __forceinline__ void ldsm_x4(uint32_t r[4], uint32_t addr) {
    asm volatile("ldmatrix.sync.aligned.m8n8.x4.shared.b16 {%0,%1,%2,%3}, [%4];"
                 : "=r"(r[0]), "=r"(r[1]), "=r"(r[2]), "=r"(r[3]) : "r"(addr));
}

__device__ __forceinline__ void mma16816(float c[4], const uint32_t a[4],
                                         const uint32_t b[2]) {
    asm volatile(
        "mma.sync.aligned.m16n8k16.row.col.f32.bf16.bf16.f32 "
        "{%0,%1,%2,%3}, {%4,%5,%6,%7}, {%8,%9}, {%0,%1,%2,%3};"
        : "+f"(c[0]), "+f"(c[1]), "+f"(c[2]), "+f"(c[3])
        : "r"(a[0]), "r"(a[1]), "r"(a[2]), "r"(a[3]), "r"(b[0]), "r"(b[1]));
}

// ---------------------------------------------------------------------------
// 0) fused: zero g_cnt/g_pos + weight prep (split/transpose/swizzle)
// ---------------------------------------------------------------------------
__global__ void __launch_bounds__(256) prep_zero_kernel(const float* __restrict__ Wl,
                                                        const float* __restrict__ Wr)
{
    int gid = blockIdx.x * 256 + threadIdx.x;
    if (gid < N_NODES) {
        g_cnt[gid] = 0;
        g_pos[gid] = 0;
    }
    if (gid < 16384) {
        int p   = gid >> 13;
        int rem = gid & 8191;
        int n   = rem >> 6;
        int k   = (rem & 63) * 2;
        const float* W = p ? Wr : Wl;
        float v0 = W[(size_t)k * 128 + n];
        float v1 = W[(size_t)(k + 1) * 128 + n];
        __nv_bfloat16 h0 = __float2bfloat16_rn(v0);
        __nv_bfloat16 h1 = __float2bfloat16_rn(v1);
        __nv_bfloat16 l0 = __float2bfloat16_rn(v0 - __bfloat162float(h0));
        __nv_bfloat16 l1 = __float2bfloat16_rn(v1 - __bfloat162float(h1));
        uint32_t off = SMEM_SWIZZLE_128B(tile_off(n, k));
        *reinterpret_cast<uint32_t*>(&g_img_hi[p][off]) = packbf(h0, h1);
        *reinterpret_cast<uint32_t*>(&g_img_lo[p][off]) = packbf(l0, l1);
    }
}

// ---------------------------------------------------------------------------
// 1) histogram of dst, 4 edges per thread
// ---------------------------------------------------------------------------
__global__ void __launch_bounds__(256) hist_kernel(const int* __restrict__ dst) {
    int i = (blockIdx.x * 256 + threadIdx.x) * 4;
    if (i < N_EDGES) {
        int4 d = *reinterpret_cast<const int4*>(dst + i);
        atomicAdd(&g_cnt[d.x], 1);
        atomicAdd(&g_cnt[d.y], 1);
        atomicAdd(&g_cnt[d.z], 1);
        atomicAdd(&g_cnt[d.w], 1);
    }
}

// ---------------------------------------------------------------------------
// 2a/2b) two-level scan
// ---------------------------------------------------------------------------
__global__ void scan1_kernel() {
    __shared__ int sh[SCAN_BLK];
    int t = threadIdx.x;
    int i = blockIdx.x * SCAN_BLK + t;
    int v = (i < N_NODES) ? g_cnt[i] : 0;
    sh[t] = v;
    __syncthreads();
    #pragma unroll
    for (int off = 1; off < SCAN_BLK; off <<= 1) {
        int t2 = (t >= off) ? sh[t - off] : 0;
        __syncthreads();
        sh[t] += t2;
        __syncthreads();
    }
    if (i < N_NODES) g_start[i] = sh[t] - v;
    if (t == SCAN_BLK - 1) g_bsum[blockIdx.x] = sh[t];
}

__global__ void scan2_kernel() {
    __shared__ int sh[SCAN_BLK];
    int t = threadIdx.x;
    int v = (t < N_SCAN_BLOCKS) ? g_bsum[t] : 0;
    sh[t] = v;
    __syncthreads();
    #pragma unroll
    for (int off = 1; off < SCAN_BLK; off <<= 1) {
        int t2 = (t >= off) ? sh[t - off] : 0;
        __syncthreads();
        sh[t] += t2;
        __syncthreads();
    }
    if (t < N_SCAN_BLOCKS) g_boff[t] = sh[t] - v;
}

// ---------------------------------------------------------------------------
// 3) fill dst-sorted edge list, 4 edges per thread
// ---------------------------------------------------------------------------
__global__ void __launch_bounds__(256) fill_kernel(const int* __restrict__ src,
                                                   const int* __restrict__ dst) {
    int i = (blockIdx.x * 256 + threadIdx.x) * 4;
    if (i < N_EDGES) {
        int4 s = *reinterpret_cast<const int4*>(src + i);
        int4 d = *reinterpret_cast<const int4*>(dst + i);
        { int b = g_start[d.x] + g_boff[d.x >> 8]; g_esrc[b + atomicAdd(&g_pos[d.x], 1)] = s.x; }
        { int b = g_start[d.y] + g_boff[d.y >> 8]; g_esrc[b + atomicAdd(&g_pos[d.y], 1)] = s.y; }
        { int b = g_start[d.z] + g_boff[d.z >> 8]; g_esrc[b + atomicAdd(&g_pos[d.z], 1)] = s.z; }
        { int b = g_start[d.w] + g_boff[d.w >> 8]; g_esrc[b + atomicAdd(&g_pos[d.w], 1)] = s.w; }
    }
}

// ---------------------------------------------------------------------------
// Shared GEMM machinery: 128x128 tile, 8 warps, single K=128 phase,
// split bf16 (hi*hi + hi*lo + lo*hi), fp32 accum.
// ---------------------------------------------------------------------------
#define OFF_BIAS  0
#define OFF_AHI   1024
#define OFF_ALO   (OFF_AHI + 32768)
#define OFF_BHI   (OFF_ALO + 32768)
#define OFF_BLO   (OFF_BHI + 32768)
#define SMEM_TOTAL (OFF_BLO + 32768)

// computes acc = A_block @ W_img[phase]^T for this block's 128 rows of x
__device__ __forceinline__ void gemm_core(
    char* smem, uint32_t smem_base, int phase,
    const float4* __restrict__ arow4,   // this thread's A source row (clamped)
    int tid, float acc[2][8][4])
{
    const int wid  = tid >> 5;
    const int lane = tid & 31;
    const int wm = (wid & 3) * 32;
    const int wn = (wid >> 2) * 64;
    const int am = tid & 127;
    const int kh = tid >> 7;

    const int a_r = ((lane >> 3) & 1) * 8 + (lane & 7);
    const int a_c = ((lane >> 4) & 1) * 8;
    const int b_r = ((lane >> 4) & 1) * 8 + (lane & 7);
    const int b_c = ((lane >> 3) & 1) * 8;

    // copy B images
    {
        const uint4* shi = reinterpret_cast<const uint4*>(g_img_hi[phase]);
        const uint4* slo = reinterpret_cast<const uint4*>(g_img_lo[phase]);
        uint4* dhi = reinterpret_cast<uint4*>(smem + OFF_BHI);
        uint4* dlo = reinterpret_cast<uint4*>(smem + OFF_BLO);
        #pragma unroll
        for (int i = 0; i < 8; i++) {
            dhi[tid + 256 * i] = shi[tid + 256 * i];
            dlo[tid + 256 * i] = slo[tid + 256 * i];
        }
    }
    // convert A half-row
    {
        #pragma unroll
        for (int g = 0; g < 8; g++) {
            int kbase = kh * 64 + g * 8;
            float4 v0 = arow4[kbase / 4];
            float4 v1 = arow4[kbase / 4 + 1];
            float vv[8] = {v0.x, v0.y, v0.z, v0.w, v1.x, v1.y, v1.z, v1.w};
            uint32_t hp[4], lp[4];
            #pragma unroll
            for (int j = 0; j < 4; j++) {
                __nv_bfloat16 h0 = __float2bfloat16_rn(vv[2 * j]);
                __nv_bfloat16 h1 = __float2bfloat16_rn(vv[2 * j + 1]);
                __nv_bfloat16 l0 = __float2bfloat16_rn(vv[2 * j] - __bfloat162float(h0));
                __nv_bfloat16 l1 = __float2bfloat16_rn(vv[2 * j + 1] - __bfloat162float(h1));
                hp[j] = packbf(h0, h1);
                lp[j] = packbf(l0, l1);
            }
            uint32_t off = SMEM_SWIZZLE_128B(tile_off(am, kbase));
            *reinterpret_cast<uint4*>(smem + OFF_AHI + off) = make_uint4(hp[0], hp[1], hp[2], hp[3]);
            *reinterpret_cast<uint4*>(smem + OFF_ALO + off) = make_uint4(lp[0], lp[1], lp[2], lp[3]);
        }
    }
    __syncthreads();

    #pragma unroll 1
    for (int ks = 0; ks < 8; ks++) {
        const int kb = ks * 16;
        uint32_t ah[2][4], al[2][4], bh[4][4], bl[4][4];
        #pragma unroll
        for (int mt = 0; mt < 2; mt++) {
            uint32_t o = SMEM_SWIZZLE_128B(tile_off(wm + mt * 16 + a_r, kb + a_c));
            ldsm_x4(ah[mt], smem_base + OFF_AHI + o);
            ldsm_x4(al[mt], smem_base + OFF_ALO + o);
        }
        #pragma unroll
        for (int j = 0; j < 4; j++) {
            uint32_t o = SMEM_SWIZZLE_128B(tile_off(wn + j * 16 + b_r, kb + b_c));
            ldsm_x4(bh[j], smem_base + OFF_BHI + o);
            ldsm_x4(bl[j], smem_base + OFF_BLO + o);
        }
        #pragma unroll
        for (int mt = 0; mt < 2; mt++)
            #pragma unroll
            for (int j = 0; j < 4; j++) {
                mma16816(acc[mt][2 * j],     ah[mt], &bh[j][0]);
                mma16816(acc[mt][2 * j + 1], ah[mt], &bh[j][2]);
                mma16816(acc[mt][2 * j],     ah[mt], &bl[j][0]);
                mma16816(acc[mt][2 * j + 1], ah[mt], &bl[j][2]);
                mma16816(acc[mt][2 * j],     al[mt], &bh[j][0]);
                mma16816(acc[mt][2 * j + 1], al[mt], &bh[j][2]);
            }
    }
}

// ---------------------------------------------------------------------------
// 4) GEMM1:  g_y = bf16( x @ W_l )
// ---------------------------------------------------------------------------
__global__ void __launch_bounds__(256, 1) gemm1_kernel(const float* __restrict__ x)
{
    extern __shared__ __align__(1024) char smem[];
    const uint32_t smem_base = smem_to_u32(smem);
    const int tid  = threadIdx.x;
    const int wid  = tid >> 5;
    const int lane = tid & 31;
    const int row0 = blockIdx.x * 128;
    const int wm = (wid & 3) * 32;
    const int wn = (wid >> 2) * 64;

    int ar = row0 + (tid & 127);
    if (ar >= N_NODES) ar = N_NODES - 1;
    const float4* arow4 = reinterpret_cast<const float4*>(x + (size_t)ar * D);

    float acc[2][8][4];
    #pragma unroll
    for (int mt = 0; mt < 2; mt++)
        #pragma unroll
        for (int nt = 0; nt < 8; nt++)
            #pragma unroll
            for (int j = 0; j < 4; j++) acc[mt][nt][j] = 0.f;

    gemm_core(smem, smem_base, 0, arow4, tid, acc);

    #pragma unroll
    for (int mt = 0; mt < 2; mt++) {
        #pragma unroll
        for (int nt = 0; nt < 8; nt++) {
            int c  = wn + nt * 8 + (lane & 3) * 2;
            int r0 = row0 + wm + mt * 16 + (lane >> 2);
            int r1 = r0 + 8;
            if (r0 < N_NODES)
                *reinterpret_cast<uint32_t*>(&g_y[(size_t)r0 * D + c]) =
                    packbf(__float2bfloat16_rn(acc[mt][nt][0]),
                           __float2bfloat16_rn(acc[mt][nt][1]));
            if (r1 < N_NODES)
                *reinterpret_cast<uint32_t*>(&g_y[(size_t)r1 * D + c]) =
                    packbf(__float2bfloat16_rn(acc[mt][nt][2]),
                           __float2bfloat16_rn(acc[mt][nt][3]));
        }
    }
}

// ---------------------------------------------------------------------------
// 5) gather on bf16 y: one warp per node, lane = 4 bf16 cols (8 B), MLP=8.
//    writes fp32 mean into g_mean.
// ---------------------------------------------------------------------------
__global__ void __launch_bounds__(256) gather_kernel()
{
    int node = (blockIdx.x * blockDim.x + threadIdx.x) >> 5;
    int lane = threadIdx.x & 31;
    if (node >= N_NODES) return;

    int start = g_start[node] + g_boff[node >> 8];
    int deg   = g_cnt[node];
    int end   = start + deg;

    float4 acc = make_float4(0.f, 0.f, 0.f, 0.f);
    int e = start;
    for (; e + 8 <= end; e += 8) {
        int idx[8];
        #pragma unroll
        for (int j = 0; j < 8; j++) idx[j] = __ldg(&g_esrc[e + j]);
        uint2 u[8];
        #pragma unroll
        for (int j = 0; j < 8; j++)
            u[j] = *reinterpret_cast<const uint2*>(&g_y[(size_t)idx[j] * D + lane * 4]);
        #pragma unroll
        for (int j = 0; j < 8; j++) {
            float2 p0 = __bfloat1622float2(*reinterpret_cast<__nv_bfloat162*>(&u[j].x));
            float2 p1 = __bfloat1622float2(*reinterpret_cast<__nv_bfloat162*>(&u[j].y));
            acc.x += p0.x; acc.y += p0.y; acc.z += p1.x; acc.w += p1.y;
        }
    }
    for (; e < end; e++) {
        int i0 = __ldg(&g_esrc[e]);
        uint2 u = *reinterpret_cast<const uint2*>(&g_y[(size_t)i0 * D + lane * 4]);
        float2 p0 = __bfloat1622float2(*reinterpret_cast<__nv_bfloat162*>(&u.x));
        float2 p1 = __bfloat1622float2(*reinterpret_cast<__nv_bfloat162*>(&u.y));
        acc.x += p0.x; acc.y += p0.y; acc.z += p1.x; acc.w += p1.y;
    }

    float rdeg = 1.0f / fmaxf((float)deg, 1.0f);
    acc.x *= rdeg; acc.y *= rdeg; acc.z *= rdeg; acc.w *= rdeg;
    *reinterpret_cast<float4*>(&g_mean[(size_t)node * D + lane * 4]) = acc;
}

// ---------------------------------------------------------------------------
// 6) GEMM2 + epilogue:  out = x + relu( x @ W_r + g_mean + b )
// ---------------------------------------------------------------------------
__global__ void __launch_bounds__(256, 1) gemm2_kernel(
    const float* __restrict__ x,
    const float* __restrict__ bias,
    float* __restrict__ out)
{
    extern __shared__ __align__(1024) char smem[];
    const uint32_t smem_base = smem_to_u32(smem);
    const int tid  = threadIdx.x;
    const int wid  = tid >> 5;
    const int lane = tid & 31;
    const int row0 = blockIdx.x * 128;
    const int wm = (wid & 3) * 32;
    const int wn = (wid >> 2) * 64;

    if (tid < 128) reinterpret_cast<float*>(smem + OFF_BIAS)[tid] = bias[tid];

    int ar = row0 + (tid & 127);
    if (ar >= N_NODES) ar = N_NODES - 1;
    const float4* arow4 = reinterpret_cast<const float4*>(x + (size_t)ar * D);

    float acc[2][8][4];
    #pragma unroll
    for (int mt = 0; mt < 2; mt++)
        #pragma unroll
        for (int nt = 0; nt < 8; nt++)
            #pragma unroll
            for (int j = 0; j < 4; j++) acc[mt][nt][j] = 0.f;

    __syncthreads();   // bias visible before smem reuse barrier inside core
    gemm_core(smem, smem_base, 1, arow4, tid, acc);

    const float* bsp = reinterpret_cast<const float*>(smem + OFF_BIAS);
    #pragma unroll
    for (int mt = 0; mt < 2; mt++) {
        #pragma unroll
        for (int nt = 0; nt < 8; nt++) {
            int c  = wn + nt * 8 + (lane & 3) * 2;
            float2 bv = *reinterpret_cast<const float2*>(bsp + c);
            int r0 = row0 + wm + mt * 16 + (lane >> 2);
            int r1 = r0 + 8;
            if (r0 < N_NODES) {
                const float2 xv = *reinterpret_cast<const float2*>(x + (size_t)r0 * D + c);
                const float2 mv = *reinterpret_cast<const float2*>(g_mean + (size_t)r0 * D + c);
                float2 o;
                o.x = xv.x + fmaxf(acc[mt][nt][0] + mv.x + bv.x, 0.f);
                o.y = xv.y + fmaxf(acc[mt][nt][1] + mv.y + bv.y, 0.f);
                *reinterpret_cast<float2*>(out + (size_t)r0 * D + c) = o;
            }
            if (r1 < N_NODES) {
                const float2 xv = *reinterpret_cast<const float2*>(x + (size_t)r1 * D + c);
                const float2 mv = *reinterpret_cast<const float2*>(g_mean + (size_t)r1 * D + c);
                float2 o;
                o.x = xv.x + fmaxf(acc[mt][nt][2] + mv.x + bv.x, 0.f);
                o.y = xv.y + fmaxf(acc[mt][nt][3] + mv.y + bv.y, 0.f);
                *reinterpret_cast<float2*>(out + (size_t)r1 * D + c) = o;
            }
        }
    }
}

// ---------------------------------------------------------------------------
extern "C" void kernel_launch(void* const* d_in, const int* in_sizes, int n_in,
                              void* d_out, int out_size)
{
    const float* x  = (const float*)d_in[0];
    const int*   ei = (const int*)d_in[1];      // [2, E]
    const float* Wl = (const float*)d_in[2];
    const float* bl = (const float*)d_in[3];
    const float* Wr = (const float*)d_in[4];
    float* out = (float*)d_out;

    const int* src = ei;
    const int* dst = ei + N_EDGES;

    prep_zero_kernel<<<(N_NODES + 255) / 256, 256>>>(Wl, Wr);      // 0
    hist_kernel<<<(N_EDGES / 4 + 255) / 256, 256>>>(dst);          // 1
    scan1_kernel<<<N_SCAN_BLOCKS, SCAN_BLK>>>();                   // 2
    scan2_kernel<<<1, SCAN_BLK>>>();                               // 3
    fill_kernel<<<(N_EDGES / 4 + 255) / 256, 256>>>(src, dst);     // 4

    {
        cudaFuncSetAttribute(gemm1_kernel,
                             cudaFuncAttributeMaxDynamicSharedMemorySize, SMEM_TOTAL);
        int grid = (N_NODES + 127) / 128;
        gemm1_kernel<<<grid, 256, SMEM_TOTAL>>>(x);                // 5
    }
    {
        long long threads = (long long)N_NODES * 32;
        int blocks = (int)((threads + 255) / 256);
        gather_kernel<<<blocks, 256>>>();                          // 6
    }
    {
        cudaFuncSetAttribute(gemm2_kernel,
                             cudaFuncAttributeMaxDynamicSharedMemorySize, SMEM_TOTAL);
        int grid = (N_NODES + 127) / 128;
        gemm2_kernel<<<grid, 256, SMEM_TOTAL>>>(x, bl, out);       // 7
    }
}

// round 10
// speedup vs baseline: 1.1192x; 1.1192x over previous
#include <cuda_runtime.h>
#include <cuda_bf16.h>
#include <cstdint>

#define N_NODES 50000
#define D 128
#define N_EDGES 625000
#define SCAN_BLK 256
#define N_SCAN_BLOCKS ((N_NODES + SCAN_BLK - 1) / SCAN_BLK)   // 196
#define NPAIRS (N_NODES * D / 2)                              // 3.2M bf16 pairs

// Scratch (no cudaMalloc allowed)
__device__ float g_mean[(size_t)N_NODES * D];            // 25.6 MB
__device__ __nv_bfloat16 g_xb[(size_t)N_NODES * D];      // 12.8 MB: bf16 mirror of x
__device__ int   g_cnt[N_NODES];
__device__ int   g_start[N_NODES];
__device__ int   g_pos[N_NODES];
__device__ int   g_bsum[N_SCAN_BLOCKS];
__device__ int   g_boff[N_SCAN_BLOCKS];
__device__ int   g_esrc[N_EDGES];
// Pre-swizzled bf16 weight images: [phase][32KB], phase 0 = W_l^T, 1 = W_r^T
__device__ __align__(16) uint8_t g_img_hi[2][32768];
__device__ __align__(16) uint8_t g_img_lo[2][32768];

// ---------------------------------------------------------------------------
// helpers
// ---------------------------------------------------------------------------
__device__ __forceinline__ uint32_t smem_to_u32(const void* p) {
    uint32_t a;
    asm("{ .reg .u64 t; cvta.to.shared.u64 t, %1; cvt.u32.u64 %0, t; }"
        : "=r"(a) : "l"(p));
    return a;
}
#define SMEM_SWIZZLE_128B(o) ((o) ^ (((o) >> 3) & 0x70))

__device__ __forceinline__ uint32_t tile_off(int row, int col) {
    return (uint32_t)((((row >> 3) + ((col >> 6) << 4)) << 10) +
                      ((row & 7) << 7) + ((col & 63) << 1));
}

__device__ __forceinline__ uint32_t packbf(__nv_bfloat16 a, __nv_bfloat16 b) {
    __nv_bfloat162 t;
    t.x = a; t.y = b;
    return *reinterpret_cast<uint32_t*>(&t);
}

__device__ __forceinline__ void ldsm_x4(uint32_t r[4], uint32_t addr) {
    asm volatile("ldmatrix.sync.aligned.m8n8.x4.shared.b16 {%0,%1,%2,%3}, [%4];"
                 : "=r"(r[0]), "=r"(r[1]), "=r"(r[2]), "=r"(r[3]) : "r"(addr));
}

__device__ __forceinline__ void mma16816(float c[4], const uint32_t a[4],
                                         const uint32_t b[2]) {
    asm volatile(
        "mma.sync.aligned.m16n8k16.row.col.f32.bf16.bf16.f32 "
        "{%0,%1,%2,%3}, {%4,%5,%6,%7}, {%8,%9}, {%0,%1,%2,%3};"
        : "+f"(c[0]), "+f"(c[1]), "+f"(c[2]), "+f"(c[3])
        : "r"(a[0]), "r"(a[1]), "r"(a[2]), "r"(a[3]), "r"(b[0]), "r"(b[1]));
}

// ---------------------------------------------------------------------------
// 0) fused: zero g_cnt/g_pos + weight prep + x -> bf16 mirror
// ---------------------------------------------------------------------------
__global__ void __launch_bounds__(256) prep_zero_kernel(const float* __restrict__ Wl,
                                                        const float* __restrict__ Wr,
                                                        const float* __restrict__ x)
{
    int gid = blockIdx.x * 256 + threadIdx.x;
    if (gid < N_NODES) {
        g_cnt[gid] = 0;
        g_pos[gid] = 0;
    }
    if (gid < 16384) {
        int p   = gid >> 13;
        int rem = gid & 8191;
        int n   = rem >> 6;
        int k   = (rem & 63) * 2;
        const float* W = p ? Wr : Wl;
        float v0 = W[(size_t)k * 128 + n];
        float v1 = W[(size_t)(k + 1) * 128 + n];
        __nv_bfloat16 h0 = __float2bfloat16_rn(v0);
        __nv_bfloat16 h1 = __float2bfloat16_rn(v1);
        __nv_bfloat16 l0 = __float2bfloat16_rn(v0 - __bfloat162float(h0));
        __nv_bfloat16 l1 = __float2bfloat16_rn(v1 - __bfloat162float(h1));
        uint32_t off = SMEM_SWIZZLE_128B(tile_off(n, k));
        *reinterpret_cast<uint32_t*>(&g_img_hi[p][off]) = packbf(h0, h1);
        *reinterpret_cast<uint32_t*>(&g_img_lo[p][off]) = packbf(l0, l1);
    }
    // x -> bf16 mirror: each thread converts one float2 pair
    if (gid < NPAIRS) {
        float2 v = reinterpret_cast<const float2*>(x)[gid];
        reinterpret_cast<uint32_t*>(g_xb)[gid] =
            packbf(__float2bfloat16_rn(v.x), __float2bfloat16_rn(v.y));
    }
}

// ---------------------------------------------------------------------------
// 1) histogram of dst, 4 edges per thread
// ---------------------------------------------------------------------------
__global__ void __launch_bounds__(256) hist_kernel(const int* __restrict__ dst) {
    int i = (blockIdx.x * 256 + threadIdx.x) * 4;
    if (i < N_EDGES) {
        int4 d = *reinterpret_cast<const int4*>(dst + i);
        atomicAdd(&g_cnt[d.x], 1);
        atomicAdd(&g_cnt[d.y], 1);
        atomicAdd(&g_cnt[d.z], 1);
        atomicAdd(&g_cnt[d.w], 1);
    }
}

// ---------------------------------------------------------------------------
// 2a/2b) two-level scan
// ---------------------------------------------------------------------------
__global__ void scan1_kernel() {
    __shared__ int sh[SCAN_BLK];
    int t = threadIdx.x;
    int i = blockIdx.x * SCAN_BLK + t;
    int v = (i < N_NODES) ? g_cnt[i] : 0;
    sh[t] = v;
    __syncthreads();
    #pragma unroll
    for (int off = 1; off < SCAN_BLK; off <<= 1) {
        int t2 = (t >= off) ? sh[t - off] : 0;
        __syncthreads();
        sh[t] += t2;
        __syncthreads();
    }
    if (i < N_NODES) g_start[i] = sh[t] - v;
    if (t == SCAN_BLK - 1) g_bsum[blockIdx.x] = sh[t];
}

__global__ void scan2_kernel() {
    __shared__ int sh[SCAN_BLK];
    int t = threadIdx.x;
    int v = (t < N_SCAN_BLOCKS) ? g_bsum[t] : 0;
    sh[t] = v;
    __syncthreads();
    #pragma unroll
    for (int off = 1; off < SCAN_BLK; off <<= 1) {
        int t2 = (t >= off) ? sh[t - off] : 0;
        __syncthreads();
        sh[t] += t2;
        __syncthreads();
    }
    if (t < N_SCAN_BLOCKS) g_boff[t] = sh[t] - v;
}

// ---------------------------------------------------------------------------
// 3) fill dst-sorted edge list, 4 edges per thread
// ---------------------------------------------------------------------------
__global__ void __launch_bounds__(256) fill_kernel(const int* __restrict__ src,
                                                   const int* __restrict__ dst) {
    int i = (blockIdx.x * 256 + threadIdx.x) * 4;
    if (i < N_EDGES) {
        int4 s = *reinterpret_cast<const int4*>(src + i);
        int4 d = *reinterpret_cast<const int4*>(dst + i);
        { int b = g_start[d.x] + g_boff[d.x >> 8]; g_esrc[b + atomicAdd(&g_pos[d.x], 1)] = s.x; }
        { int b = g_start[d.y] + g_boff[d.y >> 8]; g_esrc[b + atomicAdd(&g_pos[d.y], 1)] = s.y; }
        { int b = g_start[d.z] + g_boff[d.z >> 8]; g_esrc[b + atomicAdd(&g_pos[d.z], 1)] = s.z; }
        { int b = g_start[d.w] + g_boff[d.w >> 8]; g_esrc[b + atomicAdd(&g_pos[d.w], 1)] = s.w; }
    }
}

// ---------------------------------------------------------------------------
// 4) pull-aggregate on bf16 x: one warp per node, lane = 4 bf16 cols (8 B),
//    MLP=8; fp32 accumulate; writes fp32 mean.
// ---------------------------------------------------------------------------
__global__ void __launch_bounds__(256) gather_kernel()
{
    int node = (blockIdx.x * blockDim.x + threadIdx.x) >> 5;
    int lane = threadIdx.x & 31;
    if (node >= N_NODES) return;

    int start = g_start[node] + g_boff[node >> 8];
    int deg   = g_cnt[node];
    int end   = start + deg;

    float4 acc = make_float4(0.f, 0.f, 0.f, 0.f);
    int e = start;
    for (; e + 8 <= end; e += 8) {
        int idx[8];
        #pragma unroll
        for (int j = 0; j < 8; j++) idx[j] = __ldg(&g_esrc[e + j]);
        uint2 u[8];
        #pragma unroll
        for (int j = 0; j < 8; j++)
            u[j] = *reinterpret_cast<const uint2*>(&g_xb[(size_t)idx[j] * D + lane * 4]);
        #pragma unroll
        for (int j = 0; j < 8; j++) {
            float2 p0 = __bfloat1622float2(*reinterpret_cast<__nv_bfloat162*>(&u[j].x));
            float2 p1 = __bfloat1622float2(*reinterpret_cast<__nv_bfloat162*>(&u[j].y));
            acc.x += p0.x; acc.y += p0.y; acc.z += p1.x; acc.w += p1.y;
        }
    }
    for (; e < end; e++) {
        int i0 = __ldg(&g_esrc[e]);
        uint2 u = *reinterpret_cast<const uint2*>(&g_xb[(size_t)i0 * D + lane * 4]);
        float2 p0 = __bfloat1622float2(*reinterpret_cast<__nv_bfloat162*>(&u.x));
        float2 p1 = __bfloat1622float2(*reinterpret_cast<__nv_bfloat162*>(&u.y));
        acc.x += p0.x; acc.y += p0.y; acc.z += p1.x; acc.w += p1.y;
    }

    float rdeg = 1.0f / fmaxf((float)deg, 1.0f);
    acc.x *= rdeg; acc.y *= rdeg; acc.z *= rdeg; acc.w *= rdeg;
    *reinterpret_cast<float4*>(&g_mean[(size_t)node * D + lane * 4]) = acc;
}

// ---------------------------------------------------------------------------
// 5) HMMA GEMM (round-8 measured good, unchanged):
//    out = x + relu( g_mean @ W_l + x @ W_r + b )
// ---------------------------------------------------------------------------
#define OFF_BIAS  0
#define OFF_AHI   1024
#define OFF_ALO   (OFF_AHI + 32768)
#define OFF_BHI   (OFF_ALO + 32768)
#define OFF_BLO   (OFF_BHI + 32768)
#define SMEM_TOTAL (OFF_BLO + 32768)

__global__ void __launch_bounds__(256, 1) gemm_mma_kernel(
    const float* __restrict__ x,
    const float* __restrict__ bias,
    float* __restrict__ out)
{
    extern __shared__ __align__(1024) char smem[];
    const uint32_t smem_base = smem_to_u32(smem);
    const int tid  = threadIdx.x;
    const int wid  = tid >> 5;
    const int lane = tid & 31;
    const int row0 = blockIdx.x * 128;

    const int wm = (wid & 3) * 32;
    const int wn = (wid >> 2) * 64;

    if (tid < 128) reinterpret_cast<float*>(smem + OFF_BIAS)[tid] = bias[tid];

    const int am = tid & 127;
    const int kh = tid >> 7;
    int ar = row0 + am;
    if (ar >= N_NODES) ar = N_NODES - 1;
    const float4* mean4 = reinterpret_cast<const float4*>(g_mean + (size_t)ar * D);
    const float4* x4r   = reinterpret_cast<const float4*>(x + (size_t)ar * D);

    const int a_r  = ((lane >> 3) & 1) * 8 + (lane & 7);
    const int a_c  = ((lane >> 4) & 1) * 8;
    const int b_r  = ((lane >> 4) & 1) * 8 + (lane & 7);
    const int b_c  = ((lane >> 3) & 1) * 8;

    float acc[2][8][4];
    #pragma unroll
    for (int mt = 0; mt < 2; mt++)
        #pragma unroll
        for (int nt = 0; nt < 8; nt++)
            #pragma unroll
            for (int j = 0; j < 4; j++)
                acc[mt][nt][j] = 0.f;

    #pragma unroll 1
    for (int phase = 0; phase < 2; phase++) {
        __syncthreads();

        {
            const uint4* shi = reinterpret_cast<const uint4*>(g_img_hi[phase]);
            const uint4* slo = reinterpret_cast<const uint4*>(g_img_lo[phase]);
            uint4* dhi = reinterpret_cast<uint4*>(smem + OFF_BHI);
            uint4* dlo = reinterpret_cast<uint4*>(smem + OFF_BLO);
            #pragma unroll
            for (int i = 0; i < 8; i++) {
                dhi[tid + 256 * i] = shi[tid + 256 * i];
                dlo[tid + 256 * i] = slo[tid + 256 * i];
            }
        }
        {
            const float4* srow = phase ? x4r : mean4;
            #pragma unroll
            for (int g = 0; g < 8; g++) {
                int kbase = kh * 64 + g * 8;
                float4 v0 = srow[kbase / 4];
                float4 v1 = srow[kbase / 4 + 1];
                float vv[8] = {v0.x, v0.y, v0.z, v0.w, v1.x, v1.y, v1.z, v1.w};
                uint32_t hp[4], lp[4];
                #pragma unroll
                for (int j = 0; j < 4; j++) {
                    __nv_bfloat16 h0 = __float2bfloat16_rn(vv[2 * j]);
                    __nv_bfloat16 h1 = __float2bfloat16_rn(vv[2 * j + 1]);
                    __nv_bfloat16 l0 = __float2bfloat16_rn(vv[2 * j] - __bfloat162float(h0));
                    __nv_bfloat16 l1 = __float2bfloat16_rn(vv[2 * j + 1] - __bfloat162float(h1));
                    hp[j] = packbf(h0, h1);
                    lp[j] = packbf(l0, l1);
                }
                uint32_t off = SMEM_SWIZZLE_128B(tile_off(am, kbase));
                *reinterpret_cast<uint4*>(smem + OFF_AHI + off) =
                    make_uint4(hp[0], hp[1], hp[2], hp[3]);
                *reinterpret_cast<uint4*>(smem + OFF_ALO + off) =
                    make_uint4(lp[0], lp[1], lp[2], lp[3]);
            }
        }
        __syncthreads();

        #pragma unroll 1
        for (int ks = 0; ks < 8; ks++) {
            const int kb = ks * 16;
            uint32_t ah[2][4], al[2][4], bh[4][4], bl[4][4];
            #pragma unroll
            for (int mt = 0; mt < 2; mt++) {
                uint32_t o = SMEM_SWIZZLE_128B(tile_off(wm + mt * 16 + a_r, kb + a_c));
                ldsm_x4(ah[mt], smem_base + OFF_AHI + o);
                ldsm_x4(al[mt], smem_base + OFF_ALO + o);
            }
            #pragma unroll
            for (int j = 0; j < 4; j++) {
                uint32_t o = SMEM_SWIZZLE_128B(tile_off(wn + j * 16 + b_r, kb + b_c));
                ldsm_x4(bh[j], smem_base + OFF_BHI + o);
                ldsm_x4(bl[j], smem_base + OFF_BLO + o);
            }
            #pragma unroll
            for (int mt = 0; mt < 2; mt++)
                #pragma unroll
                for (int j = 0; j < 4; j++) {
                    mma16816(acc[mt][2 * j],     ah[mt], &bh[j][0]);
                    mma16816(acc[mt][2 * j + 1], ah[mt], &bh[j][2]);
                    mma16816(acc[mt][2 * j],     ah[mt], &bl[j][0]);
                    mma16816(acc[mt][2 * j + 1], ah[mt], &bl[j][2]);
                    mma16816(acc[mt][2 * j],     al[mt], &bh[j][0]);
                    mma16816(acc[mt][2 * j + 1], al[mt], &bh[j][2]);
                }
        }
    }

    const float* bsp = reinterpret_cast<const float*>(smem + OFF_BIAS);
    #pragma unroll
    for (int mt = 0; mt < 2; mt++) {
        #pragma unroll
        for (int nt = 0; nt < 8; nt++) {
            int c  = wn + nt * 8 + (lane & 3) * 2;
            float2 bv = *reinterpret_cast<const float2*>(bsp + c);
            int r0 = row0 + wm + mt * 16 + (lane >> 2);
            int r1 = r0 + 8;
            if (r0 < N_NODES) {
                const float2 xv = *reinterpret_cast<const float2*>(x + (size_t)r0 * D + c);
                float2 o;
                o.x = xv.x + fmaxf(acc[mt][nt][0] + bv.x, 0.f);
                o.y = xv.y + fmaxf(acc[mt][nt][1] + bv.y, 0.f);
                *reinterpret_cast<float2*>(out + (size_t)r0 * D + c) = o;
            }
            if (r1 < N_NODES) {
                const float2 xv = *reinterpret_cast<const float2*>(x + (size_t)r1 * D + c);
                float2 o;
                o.x = xv.x + fmaxf(acc[mt][nt][2] + bv.x, 0.f);
                o.y = xv.y + fmaxf(acc[mt][nt][3] + bv.y, 0.f);
                *reinterpret_cast<float2*>(out + (size_t)r1 * D + c) = o;
            }
        }
    }
}

// ---------------------------------------------------------------------------
extern "C" void kernel_launch(void* const* d_in, const int* in_sizes, int n_in,
                              void* d_out, int out_size)
{
    const float* x  = (const float*)d_in[0];
    const int*   ei = (const int*)d_in[1];      // [2, E]
    const float* Wl = (const float*)d_in[2];
    const float* bl = (const float*)d_in[3];
    const float* Wr = (const float*)d_in[4];
    float* out = (float*)d_out;

    const int* src = ei;
    const int* dst = ei + N_EDGES;

    prep_zero_kernel<<<(NPAIRS + 255) / 256, 256>>>(Wl, Wr, x);    // 0
    hist_kernel<<<(N_EDGES / 4 + 255) / 256, 256>>>(dst);          // 1
    scan1_kernel<<<N_SCAN_BLOCKS, SCAN_BLK>>>();                   // 2
    scan2_kernel<<<1, SCAN_BLK>>>();                               // 3
    fill_kernel<<<(N_EDGES / 4 + 255) / 256, 256>>>(src, dst);     // 4

    {
        long long threads = (long long)N_NODES * 32;
        int blocks = (int)((threads + 255) / 256);
        gather_kernel<<<blocks, 256>>>();                          // 5
    }

    {
        cudaFuncSetAttribute(gemm_mma_kernel,
                             cudaFuncAttributeMaxDynamicSharedMemorySize,
                             SMEM_TOTAL);
        int grid = (N_NODES + 127) / 128;   // 391
        gemm_mma_kernel<<<grid, 256, SMEM_TOTAL>>>(x, bl, out);    // 6
    }
}

// round 12
// speedup vs baseline: 1.1858x; 1.0595x over previous
#include <cuda_runtime.h>
#include <cuda_bf16.h>
#include <cstdint>

#define N_NODES 50000
#define D 128
#define N_EDGES 625000
#define SCAN_BLK 256
#define N_SCAN_BLOCKS ((N_NODES + SCAN_BLK - 1) / SCAN_BLK)   // 196

// Scratch (no cudaMalloc allowed)
__device__ float g_mean[(size_t)N_NODES * D];   // 25.6 MB
__device__ int   g_cnt[N_NODES];
__device__ int   g_start[N_NODES];              // final CSR segment starts
__device__ int   g_pos[N_NODES];                // fill cursor (zeroed)
__device__ int   g_total;                       // bump allocator for block bases
__device__ int   g_esrc[N_EDGES];
// Pre-swizzled bf16 weight images: [phase][32KB], phase 0 = W_l^T, 1 = W_r^T
__device__ __align__(16) uint8_t g_img_hi[2][32768];
__device__ __align__(16) uint8_t g_img_lo[2][32768];

// ---------------------------------------------------------------------------
// helpers
// ---------------------------------------------------------------------------
__device__ __forceinline__ uint32_t smem_to_u32(const void* p) {
    uint32_t a;
    asm("{ .reg .u64 t; cvta.to.shared.u64 t, %1; cvt.u32.u64 %0, t; }"
        : "=r"(a) : "l"(p));
    return a;
}
#define SMEM_SWIZZLE_128B(o) ((o) ^ (((o) >> 3) & 0x70))

// blocked-atom byte offset, 128-row tile (B images): atom = 8r x 64c
__device__ __forceinline__ uint32_t tile_off(int row, int col) {
    return (uint32_t)((((row >> 3) + ((col >> 6) << 4)) << 10) +
                      ((row & 7) << 7) + ((col & 63) << 1));
}
// blocked-atom byte offset, 64-row tile (A tiles): 8 row-atoms per col-block
__device__ __forceinline__ uint32_t tile_off64(int row, int col) {
    return (uint32_t)((((row >> 3) + ((col >> 6) << 3)) << 10) +
                      ((row & 7) << 7) + ((col & 63) << 1));
}

__device__ __forceinline__ uint32_t packbf(__nv_bfloat16 a, __nv_bfloat16 b) {
    __nv_bfloat162 t;
    t.x = a; t.y = b;
    return *reinterpret_cast<uint32_t*>(&t);
}

__device__ __forceinline__ void ldsm_x4(uint32_t r[4], uint32_t addr) {
    asm volatile("ldmatrix.sync.aligned.m8n8.x4.shared.b16 {%0,%1,%2,%3}, [%4];"
                 : "=r"(r[0]), "=r"(r[1]), "=r"(r[2]), "=r"(r[3]) : "r"(addr));
}

__device__ __forceinline__ void mma16816(float c[4], const uint32_t a[4],
                                         const uint32_t b[2]) {
    asm volatile(
        "mma.sync.aligned.m16n8k16.row.col.f32.bf16.bf16.f32 "
        "{%0,%1,%2,%3}, {%4,%5,%6,%7}, {%8,%9}, {%0,%1,%2,%3};"
        : "+f"(c[0]), "+f"(c[1]), "+f"(c[2]), "+f"(c[3])
        : "r"(a[0]), "r"(a[1]), "r"(a[2]), "r"(a[3]), "r"(b[0]), "r"(b[1]));
}

// ---------------------------------------------------------------------------
// 0) fused: zero g_cnt/g_pos/g_total + weight prep (split/transpose/swizzle)
// ---------------------------------------------------------------------------
__global__ void __launch_bounds__(256) prep_zero_kernel(const float* __restrict__ Wl,
                                                        const float* __restrict__ Wr)
{
    int gid = blockIdx.x * 256 + threadIdx.x;
    if (gid == 0) g_total = 0;
    if (gid < N_NODES) {
        g_cnt[gid] = 0;
        g_pos[gid] = 0;
    }
    if (gid < 16384) {
        int p   = gid >> 13;
        int rem = gid & 8191;
        int n   = rem >> 6;
        int k   = (rem & 63) * 2;
        const float* W = p ? Wr : Wl;
        float v0 = W[(size_t)k * 128 + n];
        float v1 = W[(size_t)(k + 1) * 128 + n];
        __nv_bfloat16 h0 = __float2bfloat16_rn(v0);
        __nv_bfloat16 h1 = __float2bfloat16_rn(v1);
        __nv_bfloat16 l0 = __float2bfloat16_rn(v0 - __bfloat162float(h0));
        __nv_bfloat16 l1 = __float2bfloat16_rn(v1 - __bfloat162float(h1));
        uint32_t off = SMEM_SWIZZLE_128B(tile_off(n, k));
        *reinterpret_cast<uint32_t*>(&g_img_hi[p][off]) = packbf(h0, h1);
        *reinterpret_cast<uint32_t*>(&g_img_lo[p][off]) = packbf(l0, l1);
    }
}

// ---------------------------------------------------------------------------
// 1) histogram of dst, 4 edges per thread
// ---------------------------------------------------------------------------
__global__ void __launch_bounds__(256) hist_kernel(const int* __restrict__ dst) {
    int i = (blockIdx.x * 256 + threadIdx.x) * 4;
    if (i < N_EDGES) {
        int4 d = *reinterpret_cast<const int4*>(dst + i);
        atomicAdd(&g_cnt[d.x], 1);
        atomicAdd(&g_cnt[d.y], 1);
        atomicAdd(&g_cnt[d.z], 1);
        atomicAdd(&g_cnt[d.w], 1);
    }
}

// ---------------------------------------------------------------------------
// 2) single-kernel scan: per-block exclusive scan + atomic bump for the base.
//    CSR segment order across blocks is irrelevant (only per-node contiguity
//    matters), so nondeterministic block order is fine.
// ---------------------------------------------------------------------------
__global__ void scan_kernel() {
    __shared__ int sh[SCAN_BLK];
    __shared__ int base_sh;
    int t = threadIdx.x;
    int i = blockIdx.x * SCAN_BLK + t;
    int v = (i < N_NODES) ? g_cnt[i] : 0;
    sh[t] = v;
    __syncthreads();
    #pragma unroll
    for (int off = 1; off < SCAN_BLK; off <<= 1) {
        int t2 = (t >= off) ? sh[t - off] : 0;
        __syncthreads();
        sh[t] += t2;
        __syncthreads();
    }
    if (t == SCAN_BLK - 1) base_sh = atomicAdd(&g_total, sh[t]);
    __syncthreads();
    if (i < N_NODES) g_start[i] = base_sh + sh[t] - v;
}

// ---------------------------------------------------------------------------
// 3) fill dst-sorted edge list, 4 edges per thread
// ---------------------------------------------------------------------------
__global__ void __launch_bounds__(256) fill_kernel(const int* __restrict__ src,
                                                   const int* __restrict__ dst) {
    int i = (blockIdx.x * 256 + threadIdx.x) * 4;
    if (i < N_EDGES) {
        int4 s = *reinterpret_cast<const int4*>(src + i);
        int4 d = *reinterpret_cast<const int4*>(dst + i);
        g_esrc[g_start[d.x] + atomicAdd(&g_pos[d.x], 1)] = s.x;
        g_esrc[g_start[d.y] + atomicAdd(&g_pos[d.y], 1)] = s.y;
        g_esrc[g_start[d.z] + atomicAdd(&g_pos[d.z], 1)] = s.z;
        g_esrc[g_start[d.w] + atomicAdd(&g_pos[d.w], 1)] = s.w;
    }
}

// ---------------------------------------------------------------------------
// 4) pull-aggregate (R8 fp32 form): one warp per node, lane = float4, MLP=8
// ---------------------------------------------------------------------------
__global__ void __launch_bounds__(256) gather_kernel(const float4* __restrict__ x4)
{
    int node = (blockIdx.x * blockDim.x + threadIdx.x) >> 5;
    int lane = threadIdx.x & 31;
    if (node >= N_NODES) return;

    int start = g_start[node];
    int deg   = g_cnt[node];
    int end   = start + deg;

    float4 acc = make_float4(0.f, 0.f, 0.f, 0.f);
    int e = start;
    for (; e + 8 <= end; e += 8) {
        int idx[8];
        #pragma unroll
        for (int j = 0; j < 8; j++) idx[j] = __ldg(&g_esrc[e + j]);
        float4 v[8];
        #pragma unroll
        for (int j = 0; j < 8; j++) v[j] = x4[(size_t)idx[j] * (D / 4) + lane];
        acc.x += ((v[0].x + v[1].x) + (v[2].x + v[3].x)) + ((v[4].x + v[5].x) + (v[6].x + v[7].x));
        acc.y += ((v[0].y + v[1].y) + (v[2].y + v[3].y)) + ((v[4].y + v[5].y) + (v[6].y + v[7].y));
        acc.z += ((v[0].z + v[1].z) + (v[2].z + v[3].z)) + ((v[4].z + v[5].z) + (v[6].z + v[7].z));
        acc.w += ((v[0].w + v[1].w) + (v[2].w + v[3].w)) + ((v[4].w + v[5].w) + (v[6].w + v[7].w));
    }
    for (; e < end; e++) {
        int i0 = __ldg(&g_esrc[e]);
        float4 v0 = x4[(size_t)i0 * (D / 4) + lane];
        acc.x += v0.x; acc.y += v0.y; acc.z += v0.z; acc.w += v0.w;
    }

    float rdeg = 1.0f / fmaxf((float)deg, 1.0f);
    acc.x *= rdeg; acc.y *= rdeg; acc.z *= rdeg; acc.w *= rdeg;
    reinterpret_cast<float4*>(g_mean)[(size_t)node * (D / 4) + lane] = acc;
}

// ---------------------------------------------------------------------------
// 5) HMMA GEMM, BM=64 for 2 blocks/SM:
//    out = x + relu( g_mean @ W_l + x @ W_r + b )
//    64x128 block tile, 8 warps (warp tile 32x32), 2 phases of K=128,
//    split bf16 (hi*hi + hi*lo + lo*hi), fp32 accum.
// ---------------------------------------------------------------------------
#define OFF_BIAS  0
#define OFF_AHI   1024
#define OFF_ALO   (OFF_AHI + 16384)
#define OFF_BHI   (OFF_ALO + 16384)
#define OFF_BLO   (OFF_BHI + 32768)
#define SMEM_TOTAL (OFF_BLO + 32768)   // ~97.5 KB -> 2 blocks/SM

__global__ void __launch_bounds__(256, 2) gemm_mma_kernel(
    const float* __restrict__ x,
    const float* __restrict__ bias,
    float* __restrict__ out)
{
    extern __shared__ __align__(1024) char smem[];
    const uint32_t smem_base = smem_to_u32(smem);
    const int tid  = threadIdx.x;
    const int wid  = tid >> 5;
    const int lane = tid & 31;
    const int row0 = blockIdx.x * 64;

    // 2 warps along M, 4 along N
    const int wm = (wid & 1) * 32;
    const int wn = (wid >> 1) * 32;

    if (tid < 128) reinterpret_cast<float*>(smem + OFF_BIAS)[tid] = bias[tid];

    // A-convert assignment: row = tid&63, quarter kh = tid>>6 (32 cols each)
    const int am = tid & 63;
    const int kh = tid >> 6;             // 0..3
    int ar = row0 + am;
    if (ar >= N_NODES) ar = N_NODES - 1;
    const float4* mean4 = reinterpret_cast<const float4*>(g_mean + (size_t)ar * D);
    const float4* x4r   = reinterpret_cast<const float4*>(x + (size_t)ar * D);

    const int a_r  = ((lane >> 3) & 1) * 8 + (lane & 7);
    const int a_c  = ((lane >> 4) & 1) * 8;
    const int b_r  = ((lane >> 4) & 1) * 8 + (lane & 7);
    const int b_c  = ((lane >> 3) & 1) * 8;

    float acc[2][4][4];
    #pragma unroll
    for (int mt = 0; mt < 2; mt++)
        #pragma unroll
        for (int nt = 0; nt < 4; nt++)
            #pragma unroll
            for (int j = 0; j < 4; j++)
                acc[mt][nt][j] = 0.f;

    #pragma unroll 1
    for (int phase = 0; phase < 2; phase++) {
        __syncthreads();

        // copy B images (32 KB hi + 32 KB lo)
        {
            const uint4* shi = reinterpret_cast<const uint4*>(g_img_hi[phase]);
            const uint4* slo = reinterpret_cast<const uint4*>(g_img_lo[phase]);
            uint4* dhi = reinterpret_cast<uint4*>(smem + OFF_BHI);
            uint4* dlo = reinterpret_cast<uint4*>(smem + OFF_BLO);
            #pragma unroll
            for (int i = 0; i < 8; i++) {
                dhi[tid + 256 * i] = shi[tid + 256 * i];
                dlo[tid + 256 * i] = slo[tid + 256 * i];
            }
        }
        // convert A quarter-row: 32 fp32 -> hi/lo bf16, swizzled stores
        {
            const float4* srow = phase ? x4r : mean4;
            #pragma unroll
            for (int g = 0; g < 4; g++) {
                int kbase = kh * 32 + g * 8;
                float4 v0 = srow[kbase / 4];
                float4 v1 = srow[kbase / 4 + 1];
                float vv[8] = {v0.x, v0.y, v0.z, v0.w, v1.x, v1.y, v1.z, v1.w};
                uint32_t hp[4], lp[4];
                #pragma unroll
                for (int j = 0; j < 4; j++) {
                    __nv_bfloat16 h0 = __float2bfloat16_rn(vv[2 * j]);
                    __nv_bfloat16 h1 = __float2bfloat16_rn(vv[2 * j + 1]);
                    __nv_bfloat16 l0 = __float2bfloat16_rn(vv[2 * j] - __bfloat162float(h0));
                    __nv_bfloat16 l1 = __float2bfloat16_rn(vv[2 * j + 1] - __bfloat162float(h1));
                    hp[j] = packbf(h0, h1);
                    lp[j] = packbf(l0, l1);
                }
                uint32_t off = SMEM_SWIZZLE_128B(tile_off64(am, kbase));
                *reinterpret_cast<uint4*>(smem + OFF_AHI + off) =
                    make_uint4(hp[0], hp[1], hp[2], hp[3]);
                *reinterpret_cast<uint4*>(smem + OFF_ALO + off) =
                    make_uint4(lp[0], lp[1], lp[2], lp[3]);
            }
        }
        __syncthreads();

        #pragma unroll 1
        for (int ks = 0; ks < 8; ks++) {
            const int kb = ks * 16;
            uint32_t ah[2][4], al[2][4], bh[2][4], bl[2][4];
            #pragma unroll
            for (int mt = 0; mt < 2; mt++) {
                uint32_t o = SMEM_SWIZZLE_128B(tile_off64(wm + mt * 16 + a_r, kb + a_c));
                ldsm_x4(ah[mt], smem_base + OFF_AHI + o);
                ldsm_x4(al[mt], smem_base + OFF_ALO + o);
            }
            #pragma unroll
            for (int j = 0; j < 2; j++) {
                uint32_t o = SMEM_SWIZZLE_128B(tile_off(wn + j * 16 + b_r, kb + b_c));
                ldsm_x4(bh[j], smem_base + OFF_BHI + o);
                ldsm_x4(bl[j], smem_base + OFF_BLO + o);
            }
            #pragma unroll
            for (int mt = 0; mt < 2; mt++)
                #pragma unroll
                for (int j = 0; j < 2; j++) {
                    mma16816(acc[mt][2 * j],     ah[mt], &bh[j][0]);
                    mma16816(acc[mt][2 * j + 1], ah[mt], &bh[j][2]);
                    mma16816(acc[mt][2 * j],     ah[mt], &bl[j][0]);
                    mma16816(acc[mt][2 * j + 1], ah[mt], &bl[j][2]);
                    mma16816(acc[mt][2 * j],     al[mt], &bh[j][0]);
                    mma16816(acc[mt][2 * j + 1], al[mt], &bh[j][2]);
                }
        }
    }

    const float* bsp = reinterpret_cast<const float*>(smem + OFF_BIAS);
    #pragma unroll
    for (int mt = 0; mt < 2; mt++) {
        #pragma unroll
        for (int nt = 0; nt < 4; nt++) {
            int c  = wn + nt * 8 + (lane & 3) * 2;
            float2 bv = *reinterpret_cast<const float2*>(bsp + c);
            int r0 = row0 + wm + mt * 16 + (lane >> 2);
            int r1 = r0 + 8;
            if (r0 < N_NODES) {
                const float2 xv = *reinterpret_cast<const float2*>(x + (size_t)r0 * D + c);
                float2 o;
                o.x = xv.x + fmaxf(acc[mt][nt][0] + bv.x, 0.f);
                o.y = xv.y + fmaxf(acc[mt][nt][1] + bv.y, 0.f);
                *reinterpret_cast<float2*>(out + (size_t)r0 * D + c) = o;
            }
            if (r1 < N_NODES) {
                const float2 xv = *reinterpret_cast<const float2*>(x + (size_t)r1 * D + c);
                float2 o;
                o.x = xv.x + fmaxf(acc[mt][nt][2] + bv.x, 0.f);
                o.y = xv.y + fmaxf(acc[mt][nt][3] + bv.y, 0.f);
                *reinterpret_cast<float2*>(out + (size_t)r1 * D + c) = o;
            }
        }
    }
}

// ---------------------------------------------------------------------------
extern "C" void kernel_launch(void* const* d_in, const int* in_sizes, int n_in,
                              void* d_out, int out_size)
{
    const float* x  = (const float*)d_in[0];
    const int*   ei = (const int*)d_in[1];      // [2, E]
    const float* Wl = (const float*)d_in[2];
    const float* bl = (const float*)d_in[3];
    const float* Wr = (const float*)d_in[4];
    float* out = (float*)d_out;

    const int* src = ei;
    const int* dst = ei + N_EDGES;

    prep_zero_kernel<<<(N_NODES + 255) / 256, 256>>>(Wl, Wr);      // 0
    hist_kernel<<<(N_EDGES / 4 + 255) / 256, 256>>>(dst);          // 1
    scan_kernel<<<N_SCAN_BLOCKS, SCAN_BLK>>>();                    // 2
    fill_kernel<<<(N_EDGES / 4 + 255) / 256, 256>>>(src, dst);     // 3

    {
        long long threads = (long long)N_NODES * 32;
        int blocks = (int)((threads + 255) / 256);
        gather_kernel<<<blocks, 256>>>(reinterpret_cast<const float4*>(x));  // 4
    }

    {
        cudaFuncSetAttribute(gemm_mma_kernel,
                             cudaFuncAttributeMaxDynamicSharedMemorySize,
                             SMEM_TOTAL);
        int grid = (N_NODES + 63) / 64;   // 782
        gemm_mma_kernel<<<grid, 256, SMEM_TOTAL>>>(x, bl, out);    // 5
    }
}

// round 15
// speedup vs baseline: 1.2189x; 1.0279x over previous
#include <cuda_runtime.h>
#include <cuda_bf16.h>
#include <cstdint>

#define N_NODES 50000
#define D 128
#define N_EDGES 625000
#define SCAN_BLK 256
#define N_SCAN_BLOCKS ((N_NODES + SCAN_BLK - 1) / SCAN_BLK)   // 196

// Scratch (no cudaMalloc allowed)
__device__ float g_mean[(size_t)N_NODES * D];   // 25.6 MB
__device__ int   g_cnt[N_NODES];
__device__ int   g_start[N_NODES];              // final CSR segment starts
__device__ int   g_total;                       // bump allocator for block bases
__device__ int   g_esrc[N_EDGES];
__device__ int   g_rank[N_EDGES];               // per-edge rank within its dst segment
// Pre-swizzled bf16 weight images: [phase][32KB], phase 0 = W_l^T, 1 = W_r^T
__device__ __align__(16) uint8_t g_img_hi[2][32768];
__device__ __align__(16) uint8_t g_img_lo[2][32768];

// ---------------------------------------------------------------------------
// helpers
// ---------------------------------------------------------------------------
__device__ __forceinline__ uint32_t smem_to_u32(const void* p) {
    uint32_t a;
    asm("{ .reg .u64 t; cvta.to.shared.u64 t, %1; cvt.u32.u64 %0, t; }"
        : "=r"(a) : "l"(p));
    return a;
}
#define SMEM_SWIZZLE_128B(o) ((o) ^ (((o) >> 3) & 0x70))

// blocked-atom byte offset, 128-row tile (B images)
__device__ __forceinline__ uint32_t tile_off(int row, int col) {
    return (uint32_t)((((row >> 3) + ((col >> 6) << 4)) << 10) +
                      ((row & 7) << 7) + ((col & 63) << 1));
}
// blocked-atom byte offset, 64-row tile (A tiles)
__device__ __forceinline__ uint32_t tile_off64(int row, int col) {
    return (uint32_t)((((row >> 3) + ((col >> 6) << 3)) << 10) +
                      ((row & 7) << 7) + ((col & 63) << 1));
}

__device__ __forceinline__ uint32_t packbf(__nv_bfloat16 a, __nv_bfloat16 b) {
    __nv_bfloat162 t;
    t.x = a; t.y = b;
    return *reinterpret_cast<uint32_t*>(&t);
}

__device__ __forceinline__ void ldsm_x4(uint32_t r[4], uint32_t addr) {
    asm volatile("ldmatrix.sync.aligned.m8n8.x4.shared.b16 {%0,%1,%2,%3}, [%4];"
                 : "=r"(r[0]), "=r"(r[1]), "=r"(r[2]), "=r"(r[3]) : "r"(addr));
}

__device__ __forceinline__ void mma16816(float c[4], const uint32_t a[4],
                                         const uint32_t b[2]) {
    asm volatile(
        "mma.sync.aligned.m16n8k16.row.col.f32.bf16.bf16.f32 "
        "{%0,%1,%2,%3}, {%4,%5,%6,%7}, {%8,%9}, {%0,%1,%2,%3};"
        : "+f"(c[0]), "+f"(c[1]), "+f"(c[2]), "+f"(c[3])
        : "r"(a[0]), "r"(a[1]), "r"(a[2]), "r"(a[3]), "r"(b[0]), "r"(b[1]));
}

// ---------------------------------------------------------------------------
// 0) fused: zero g_cnt/g_total + weight prep (split/transpose/swizzle)
// ---------------------------------------------------------------------------
__global__ void __launch_bounds__(256) prep_zero_kernel(const float* __restrict__ Wl,
                                                        const float* __restrict__ Wr)
{
    int gid = blockIdx.x * 256 + threadIdx.x;
    if (gid == 0) g_total = 0;
    if (gid < N_NODES) g_cnt[gid] = 0;
    if (gid < 16384) {
        int p   = gid >> 13;
        int rem = gid & 8191;
        int n   = rem >> 6;
        int k   = (rem & 63) * 2;
        const float* W = p ? Wr : Wl;
        float v0 = W[(size_t)k * 128 + n];
        float v1 = W[(size_t)(k + 1) * 128 + n];
        __nv_bfloat16 h0 = __float2bfloat16_rn(v0);
        __nv_bfloat16 h1 = __float2bfloat16_rn(v1);
        __nv_bfloat16 l0 = __float2bfloat16_rn(v0 - __bfloat162float(h0));
        __nv_bfloat16 l1 = __float2bfloat16_rn(v1 - __bfloat162float(h1));
        uint32_t off = SMEM_SWIZZLE_128B(tile_off(n, k));
        *reinterpret_cast<uint32_t*>(&g_img_hi[p][off]) = packbf(h0, h1);
        *reinterpret_cast<uint32_t*>(&g_img_lo[p][off]) = packbf(l0, l1);
    }
}

// ---------------------------------------------------------------------------
// 1) histogram of dst; the atomicAdd return value IS the edge's rank — keep it
// ---------------------------------------------------------------------------
__global__ void __launch_bounds__(256) hist_kernel(const int* __restrict__ dst) {
    int i = (blockIdx.x * 256 + threadIdx.x) * 4;
    if (i < N_EDGES) {
        int4 d = *reinterpret_cast<const int4*>(dst + i);
        int4 r;
        r.x = atomicAdd(&g_cnt[d.x], 1);
        r.y = atomicAdd(&g_cnt[d.y], 1);
        r.z = atomicAdd(&g_cnt[d.z], 1);
        r.w = atomicAdd(&g_cnt[d.w], 1);
        *reinterpret_cast<int4*>(g_rank + i) = r;
    }
}

// ---------------------------------------------------------------------------
// 2) single-kernel scan: per-block exclusive scan + atomic bump for the base
// ---------------------------------------------------------------------------
__global__ void scan_kernel() {
    __shared__ int sh[SCAN_BLK];
    __shared__ int base_sh;
    int t = threadIdx.x;
    int i = blockIdx.x * SCAN_BLK + t;
    int v = (i < N_NODES) ? g_cnt[i] : 0;
    sh[t] = v;
    __syncthreads();
    #pragma unroll
    for (int off = 1; off < SCAN_BLK; off <<= 1) {
        int t2 = (t >= off) ? sh[t - off] : 0;
        __syncthreads();
        sh[t] += t2;
        __syncthreads();
    }
    if (t == SCAN_BLK - 1) base_sh = atomicAdd(&g_total, sh[t]);
    __syncthreads();
    if (i < N_NODES) g_start[i] = base_sh + sh[t] - v;
}

// ---------------------------------------------------------------------------
// 3) fill: NO atomics — rank precomputed in hist
// ---------------------------------------------------------------------------
__global__ void __launch_bounds__(256) fill_kernel(const int* __restrict__ src,
                                                   const int* __restrict__ dst) {
    int i = (blockIdx.x * 256 + threadIdx.x) * 4;
    if (i < N_EDGES) {
        int4 s = *reinterpret_cast<const int4*>(src + i);
        int4 d = *reinterpret_cast<const int4*>(dst + i);
        int4 r = *reinterpret_cast<const int4*>(g_rank + i);
        g_esrc[g_start[d.x] + r.x] = s.x;
        g_esrc[g_start[d.y] + r.y] = s.y;
        g_esrc[g_start[d.z] + r.z] = s.z;
        g_esrc[g_start[d.w] + r.w] = s.w;
    }
}

// ---------------------------------------------------------------------------
// 4) pull-aggregate: one warp per node, lane = float4, MLP=8 then 4 then tail
// ---------------------------------------------------------------------------
__global__ void __launch_bounds__(256) gather_kernel(const float4* __restrict__ x4)
{
    int node = (blockIdx.x * blockDim.x + threadIdx.x) >> 5;
    int lane = threadIdx.x & 31;
    if (node >= N_NODES) return;

    int start = g_start[node];
    int deg   = g_cnt[node];
    int end   = start + deg;

    float4 acc = make_float4(0.f, 0.f, 0.f, 0.f);
    int e = start;
    for (; e + 8 <= end; e += 8) {
        int idx[8];
        #pragma unroll
        for (int j = 0; j < 8; j++) idx[j] = __ldg(&g_esrc[e + j]);
        float4 v[8];
        #pragma unroll
        for (int j = 0; j < 8; j++) v[j] = x4[(size_t)idx[j] * (D / 4) + lane];
        acc.x += ((v[0].x + v[1].x) + (v[2].x + v[3].x)) + ((v[4].x + v[5].x) + (v[6].x + v[7].x));
        acc.y += ((v[0].y + v[1].y) + (v[2].y + v[3].y)) + ((v[4].y + v[5].y) + (v[6].y + v[7].y));
        acc.z += ((v[0].z + v[1].z) + (v[2].z + v[3].z)) + ((v[4].z + v[5].z) + (v[6].z + v[7].z));
        acc.w += ((v[0].w + v[1].w) + (v[2].w + v[3].w)) + ((v[4].w + v[5].w) + (v[6].w + v[7].w));
    }
    if (e + 4 <= end) {
        int i0 = __ldg(&g_esrc[e]);
        int i1 = __ldg(&g_esrc[e + 1]);
        int i2 = __ldg(&g_esrc[e + 2]);
        int i3 = __ldg(&g_esrc[e + 3]);
        float4 v0 = x4[(size_t)i0 * (D / 4) + lane];
        float4 v1 = x4[(size_t)i1 * (D / 4) + lane];
        float4 v2 = x4[(size_t)i2 * (D / 4) + lane];
        float4 v3 = x4[(size_t)i3 * (D / 4) + lane];
        acc.x += (v0.x + v1.x) + (v2.x + v3.x);
        acc.y += (v0.y + v1.y) + (v2.y + v3.y);
        acc.z += (v0.z + v1.z) + (v2.z + v3.z);
        acc.w += (v0.w + v1.w) + (v2.w + v3.w);
        e += 4;
    }
    if (e < end) {
        // ≤3 remaining: issue all, then sum
        int n = end - e;
        int i0 = __ldg(&g_esrc[e]);
        int i1 = __ldg(&g_esrc[e + (n > 1 ? 1 : 0)]);
        int i2 = __ldg(&g_esrc[e + (n > 2 ? 2 : 0)]);
        float4 v0 = x4[(size_t)i0 * (D / 4) + lane];
        float4 v1 = x4[(size_t)i1 * (D / 4) + lane];
        float4 v2 = x4[(size_t)i2 * (D / 4) + lane];
        acc.x += v0.x; acc.y += v0.y; acc.z += v0.z; acc.w += v0.w;
        if (n > 1) { acc.x += v1.x; acc.y += v1.y; acc.z += v1.z; acc.w += v1.w; }
        if (n > 2) { acc.x += v2.x; acc.y += v2.y; acc.z += v2.z; acc.w += v2.w; }
    }

    float rdeg = 1.0f / fmaxf((float)deg, 1.0f);
    acc.x *= rdeg; acc.y *= rdeg; acc.z *= rdeg; acc.w *= rdeg;
    reinterpret_cast<float4*>(g_mean)[(size_t)node * (D / 4) + lane] = acc;
}

// ---------------------------------------------------------------------------
// 5) HMMA GEMM, BM=64, 2 blocks/SM:
//    out = x + relu( g_mean @ W_l + x @ W_r + b )
//    Phase 0 (mean): A plain bf16, B split  -> 2 MMA terms (error ~1.85e-4,
//      validated in rounds 9/10). Phase 1 (x): full 3-term split.
// ---------------------------------------------------------------------------
#define OFF_BIAS  0
#define OFF_AHI   1024
#define OFF_ALO   (OFF_AHI + 16384)
#define OFF_BHI   (OFF_ALO + 16384)
#define OFF_BLO   (OFF_BHI + 32768)
#define SMEM_TOTAL (OFF_BLO + 32768)   // ~97.5 KB -> 2 blocks/SM

__global__ void __launch_bounds__(256, 2) gemm_mma_kernel(
    const float* __restrict__ x,
    const float* __restrict__ bias,
    float* __restrict__ out)
{
    extern __shared__ __align__(1024) char smem[];
    const uint32_t smem_base = smem_to_u32(smem);
    const int tid  = threadIdx.x;
    const int wid  = tid >> 5;
    const int lane = tid & 31;
    const int row0 = blockIdx.x * 64;

    const int wm = (wid & 1) * 32;
    const int wn = (wid >> 1) * 32;

    if (tid < 128) reinterpret_cast<float*>(smem + OFF_BIAS)[tid] = bias[tid];

    const int am = tid & 63;
    const int kh = tid >> 6;             // 0..3
    int ar = row0 + am;
    if (ar >= N_NODES) ar = N_NODES - 1;
    const float4* mean4 = reinterpret_cast<const float4*>(g_mean + (size_t)ar * D);
    const float4* x4r   = reinterpret_cast<const float4*>(x + (size_t)ar * D);

    const int a_r  = ((lane >> 3) & 1) * 8 + (lane & 7);
    const int a_c  = ((lane >> 4) & 1) * 8;
    const int b_r  = ((lane >> 4) & 1) * 8 + (lane & 7);
    const int b_c  = ((lane >> 3) & 1) * 8;

    float acc[2][4][4];
    #pragma unroll
    for (int mt = 0; mt < 2; mt++)
        #pragma unroll
        for (int nt = 0; nt < 4; nt++)
            #pragma unroll
            for (int j = 0; j < 4; j++)
                acc[mt][nt][j] = 0.f;

    #pragma unroll 1
    for (int phase = 0; phase < 2; phase++) {
        __syncthreads();

        // copy B images (32 KB hi + 32 KB lo)
        {
            const uint4* shi = reinterpret_cast<const uint4*>(g_img_hi[phase]);
            const uint4* slo = reinterpret_cast<const uint4*>(g_img_lo[phase]);
            uint4* dhi = reinterpret_cast<uint4*>(smem + OFF_BHI);
            uint4* dlo = reinterpret_cast<uint4*>(smem + OFF_BLO);
            #pragma unroll
            for (int i = 0; i < 8; i++) {
                dhi[tid + 256 * i] = shi[tid + 256 * i];
                dlo[tid + 256 * i] = slo[tid + 256 * i];
            }
        }
        // convert A quarter-row; lo-part only needed in phase 1
        {
            const float4* srow = phase ? x4r : mean4;
            #pragma unroll
            for (int g = 0; g < 4; g++) {
                int kbase = kh * 32 + g * 8;
                float4 v0 = srow[kbase / 4];
                float4 v1 = srow[kbase / 4 + 1];
                float vv[8] = {v0.x, v0.y, v0.z, v0.w, v1.x, v1.y, v1.z, v1.w};
                uint32_t hp[4], lp[4];
                #pragma unroll
                for (int j = 0; j < 4; j++) {
                    __nv_bfloat16 h0 = __float2bfloat16_rn(vv[2 * j]);
                    __nv_bfloat16 h1 = __float2bfloat16_rn(vv[2 * j + 1]);
                    __nv_bfloat16 l0 = __float2bfloat16_rn(vv[2 * j] - __bfloat162float(h0));
                    __nv_bfloat16 l1 = __float2bfloat16_rn(vv[2 * j + 1] - __bfloat162float(h1));
                    hp[j] = packbf(h0, h1);
                    lp[j] = packbf(l0, l1);
                }
                uint32_t off = SMEM_SWIZZLE_128B(tile_off64(am, kbase));
                *reinterpret_cast<uint4*>(smem + OFF_AHI + off) =
                    make_uint4(hp[0], hp[1], hp[2], hp[3]);
                if (phase)
                    *reinterpret_cast<uint4*>(smem + OFF_ALO + off) =
                        make_uint4(lp[0], lp[1], lp[2], lp[3]);
            }
        }
        __syncthreads();

        #pragma unroll 1
        for (int ks = 0; ks < 8; ks++) {
            const int kb = ks * 16;
            uint32_t ah[2][4], al[2][4], bh[2][4], bl[2][4];
            #pragma unroll
            for (int mt = 0; mt < 2; mt++) {
                uint32_t o = SMEM_SWIZZLE_128B(tile_off64(wm + mt * 16 + a_r, kb + a_c));
                ldsm_x4(ah[mt], smem_base + OFF_AHI + o);
                if (phase) ldsm_x4(al[mt], smem_base + OFF_ALO + o);
            }
            #pragma unroll
            for (int j = 0; j < 2; j++) {
                uint32_t o = SMEM_SWIZZLE_128B(tile_off(wn + j * 16 + b_r, kb + b_c));
                ldsm_x4(bh[j], smem_base + OFF_BHI + o);
                ldsm_x4(bl[j], smem_base + OFF_BLO + o);
            }
            #pragma unroll
            for (int mt = 0; mt < 2; mt++)
                #pragma unroll
                for (int j = 0; j < 2; j++) {
                    mma16816(acc[mt][2 * j],     ah[mt], &bh[j][0]);
                    mma16816(acc[mt][2 * j + 1], ah[mt], &bh[j][2]);
                    mma16816(acc[mt][2 * j],     ah[mt], &bl[j][0]);
                    mma16816(acc[mt][2 * j + 1], ah[mt], &bl[j][2]);
                    if (phase) {
                        mma16816(acc[mt][2 * j],     al[mt], &bh[j][0]);
                        mma16816(acc[mt][2 * j + 1], al[mt], &bh[j][2]);
                    }
                }
        }
    }

    const float* bsp = reinterpret_cast<const float*>(smem + OFF_BIAS);
    #pragma unroll
    for (int mt = 0; mt < 2; mt++) {
        #pragma unroll
        for (int nt = 0; nt < 4; nt++) {
            int c  = wn + nt * 8 + (lane & 3) * 2;
            float2 bv = *reinterpret_cast<const float2*>(bsp + c);
            int r0 = row0 + wm + mt * 16 + (lane >> 2);
            int r1 = r0 + 8;
            if (r0 < N_NODES) {
                const float2 xv = *reinterpret_cast<const float2*>(x + (size_t)r0 * D + c);
                float2 o;
                o.x = xv.x + fmaxf(acc[mt][nt][0] + bv.x, 0.f);
                o.y = xv.y + fmaxf(acc[mt][nt][1] + bv.y, 0.f);
                *reinterpret_cast<float2*>(out + (size_t)r0 * D + c) = o;
            }
            if (r1 < N_NODES) {
                const float2 xv = *reinterpret_cast<const float2*>(x + (size_t)r1 * D + c);
                float2 o;
                o.x = xv.x + fmaxf(acc[mt][nt][2] + bv.x, 0.f);
                o.y = xv.y + fmaxf(acc[mt][nt][3] + bv.y, 0.f);
                *reinterpret_cast<float2*>(out + (size_t)r1 * D + c) = o;
            }
        }
    }
}

// ---------------------------------------------------------------------------
extern "C" void kernel_launch(void* const* d_in, const int* in_sizes, int n_in,
                              void* d_out, int out_size)
{
    const float* x  = (const float*)d_in[0];
    const int*   ei = (const int*)d_in[1];      // [2, E]
    const float* Wl = (const float*)d_in[2];
    const float* bl = (const float*)d_in[3];
    const float* Wr = (const float*)d_in[4];
    float* out = (float*)d_out;

    const int* src = ei;
    const int* dst = ei + N_EDGES;

    prep_zero_kernel<<<(N_NODES + 255) / 256, 256>>>(Wl, Wr);      // 0
    hist_kernel<<<(N_EDGES / 4 + 255) / 256, 256>>>(dst);          // 1
    scan_kernel<<<N_SCAN_BLOCKS, SCAN_BLK>>>();                    // 2
    fill_kernel<<<(N_EDGES / 4 + 255) / 256, 256>>>(src, dst);     // 3

    {
        long long threads = (long long)N_NODES * 32;
        int blocks = (int)((threads + 255) / 256);
        gather_kernel<<<blocks, 256>>>(reinterpret_cast<const float4*>(x));  // 4
    }

    {
        cudaFuncSetAttribute(gemm_mma_kernel,
                             cudaFuncAttributeMaxDynamicSharedMemorySize,
                             SMEM_TOTAL);
        int grid = (N_NODES + 63) / 64;   // 782
        gemm_mma_kernel<<<grid, 256, SMEM_TOTAL>>>(x, bl, out);    // 5
    }
}